// round 1
// baseline (speedup 1.0000x reference)
#include <cuda_runtime.h>
#include <math.h>

// Problem constants (from reference setup_inputs): T=1024, B=64, V=256, L=256
#define CT_T 1024
#define CT_B 64
#define CT_V 256
#define CT_L 256
#define CT_S (2 * CT_L + 1)   // 513
#define NEG_INF (-1e30f)

// Scratch (no cudaMalloc allowed)
__device__ float g_lse[CT_T * CT_B];
__device__ float g_per_loss[CT_B];

// ---------------------------------------------------------------------------
// Kernel 1: lse[t,b] = logsumexp over V of logits[t,b,:]
// One warp per (t,b) row (256 floats = 8 per lane, 2x float4).
// ---------------------------------------------------------------------------
__global__ void lse_kernel(const float* __restrict__ logits) {
    int warp = (blockIdx.x * blockDim.x + threadIdx.x) >> 5;
    int lane = threadIdx.x & 31;
    if (warp >= CT_T * CT_B) return;

    const float4* p = reinterpret_cast<const float4*>(logits + (size_t)warp * CT_V);
    float4 v0 = p[lane * 2 + 0];
    float4 v1 = p[lane * 2 + 1];

    float m = fmaxf(fmaxf(fmaxf(v0.x, v0.y), fmaxf(v0.z, v0.w)),
                    fmaxf(fmaxf(v1.x, v1.y), fmaxf(v1.z, v1.w)));
    #pragma unroll
    for (int o = 16; o > 0; o >>= 1)
        m = fmaxf(m, __shfl_xor_sync(0xFFFFFFFFu, m, o));

    float s = __expf(v0.x - m) + __expf(v0.y - m) + __expf(v0.z - m) + __expf(v0.w - m)
            + __expf(v1.x - m) + __expf(v1.y - m) + __expf(v1.z - m) + __expf(v1.w - m);
    #pragma unroll
    for (int o = 16; o > 0; o >>= 1)
        s += __shfl_xor_sync(0xFFFFFFFFu, s, o);

    if (lane == 0) g_lse[warp] = m + __logf(s);
}

// ---------------------------------------------------------------------------
// Kernel 2: CTC forward recursion. One block per batch element b.
// 512 threads; alpha in SMEM double-buffered with 2-slot NEG_INF left padding.
// Logits row staged into SMEM, double-buffered; next row prefetched into
// registers before compute to hide global latency.
// ---------------------------------------------------------------------------
__global__ __launch_bounds__(512, 1)
void ctc_forward_kernel(const int* __restrict__ labels,
                        const float* __restrict__ logits,
                        const int* __restrict__ label_length,
                        const int* __restrict__ logit_length) {
    const int b   = blockIdx.x;
    const int tid = threadIdx.x;

    __shared__ float rowbuf[2][CT_V];
    __shared__ float alphabuf[2][CT_S + 2];   // indices 0,1 = NEG_INF padding
    __shared__ int   ext[CT_S];
    __shared__ unsigned char skipok[CT_S];
    __shared__ float lse_s[CT_T];

    // Stage per-b lse column
    for (int t = tid; t < CT_T; t += 512) lse_s[t] = g_lse[t * CT_B + b];

    // Extended label sequence + skip-allowed flags
    for (int s = tid; s < CT_S; s += 512) {
        int e = 0;
        unsigned char sk = 0;
        if (s & 1) {
            e = labels[b * CT_L + (s >> 1)];
            int e2 = (s >= 3) ? labels[b * CT_L + ((s - 2) >> 1)] : -1;
            sk = (e != 0) && (e != e2);
        }
        ext[s] = e;
        skipok[s] = sk;
    }

    // NEG_INF padding for both alpha buffers (indices 0,1 never rewritten)
    for (int i = tid; i < CT_S + 2; i += 512) {
        alphabuf[0][i] = NEG_INF;
        alphabuf[1][i] = NEG_INF;
    }

    // Load logits row t=0 (256 floats = 64 float4)
    if (tid < CT_V / 4) {
        reinterpret_cast<float4*>(rowbuf[0])[tid] =
            reinterpret_cast<const float4*>(logits + ((size_t)0 * CT_B + b) * CT_V)[tid];
    }
    __syncthreads();

    const int Tb = min(max(logit_length[b], 1), CT_T);

    // alpha at t=0: only s=0 (blank) and s=1 (first label)
    if (tid == 0) {
        float l0 = lse_s[0];
        alphabuf[0][2 + 0] = rowbuf[0][0]      - l0;
        alphabuf[0][2 + 1] = rowbuf[0][ext[1]] - l0;
    }
    // Prefetch row t=1
    if (tid < CT_V / 4 && 1 < Tb) {
        reinterpret_cast<float4*>(rowbuf[1])[tid] =
            reinterpret_cast<const float4*>(logits + ((size_t)1 * CT_B + b) * CT_V)[tid];
    }
    __syncthreads();

    int cur = 0;
    for (int t = 1; t < Tb; ++t) {
        const float* row = rowbuf[t & 1];
        const float lt   = lse_s[t];
        const float* Aold = alphabuf[cur] + 2;
        float*       Anew = alphabuf[cur ^ 1] + 2;

        // Issue prefetch of row t+1 (data lands in regs; stored after compute)
        float4 pre;
        const bool doPre = (tid < CT_V / 4) && (t + 1 < Tb);
        if (doPre)
            pre = reinterpret_cast<const float4*>(
                      logits + ((size_t)(t + 1) * CT_B + b) * CT_V)[tid];

        #pragma unroll 2
        for (int s = tid; s < CT_S; s += 512) {
            float a0 = Aold[s];
            float a1 = Aold[s - 1];
            float a2 = skipok[s] ? Aold[s - 2] : NEG_INF;
            float m  = fmaxf(a0, fmaxf(a1, a2));
            float v;
            if (m <= -0.5e30f) {
                v = NEG_INF;
            } else {
                v = m + __logf(__expf(a0 - m) + __expf(a1 - m) + __expf(a2 - m));
            }
            Anew[s] = v + row[ext[s]] - lt;
        }

        if (doPre)
            reinterpret_cast<float4*>(rowbuf[(t + 1) & 1])[tid] = pre;

        cur ^= 1;
        __syncthreads();
    }

    if (tid == 0) {
        int end = 2 * label_length[b];
        if (end > CT_S - 1) end = CT_S - 1;
        const float* A = alphabuf[cur] + 2;
        float ae  = A[end];
        float ae1 = A[max(end - 1, 0)];
        float m = fmaxf(ae, ae1);
        float lp;
        if (m <= -0.5e30f) lp = NEG_INF;
        else lp = m + __logf(__expf(ae - m) + __expf(ae1 - m));
        g_per_loss[b] = -lp;
    }
}

// ---------------------------------------------------------------------------
// Kernel 3: mean over B into d_out[0]
// ---------------------------------------------------------------------------
__global__ void mean_kernel(float* __restrict__ out) {
    __shared__ float sh[2];
    int tid = threadIdx.x;        // 64 threads
    float v = g_per_loss[tid];
    #pragma unroll
    for (int o = 16; o > 0; o >>= 1)
        v += __shfl_xor_sync(0xFFFFFFFFu, v, o);
    if ((tid & 31) == 0) sh[tid >> 5] = v;
    __syncthreads();
    if (tid == 0) out[0] = (sh[0] + sh[1]) * (1.0f / CT_B);
}

// ---------------------------------------------------------------------------
extern "C" void kernel_launch(void* const* d_in, const int* in_sizes, int n_in,
                              void* d_out, int out_size) {
    const int*   labels       = (const int*)d_in[0];   // [B, L]
    const float* logits       = (const float*)d_in[1]; // [T, B, V]
    const int*   label_length = (const int*)d_in[2];   // [B]
    const int*   logit_length = (const int*)d_in[3];   // [B]
    float*       out          = (float*)d_out;

    // Kernel 1: one warp per (t,b) row; 8 warps per block
    {
        int rows = CT_T * CT_B;
        int threads = 256;
        int blocks = (rows * 32 + threads - 1) / threads;
        lse_kernel<<<blocks, threads>>>(logits);
    }
    // Kernel 2: one block per batch element
    ctc_forward_kernel<<<CT_B, 512>>>(labels, logits, label_length, logit_length);
    // Kernel 3: mean
    mean_kernel<<<1, CT_B>>>(out);
}